// round 1
// baseline (speedup 1.0000x reference)
#include <cuda_runtime.h>
#include <cstdio>

// ---------------------------------------------------------------------------
// Problem constants
// ---------------------------------------------------------------------------
#define NPTS   16384      // N*P
#define KNB    16         // K neighbors
#define NDIMS  3
#define C_IN   128
#define C_MID  64
#define C_OUT  256
#define DMUL   2
#define C_CAT  192        // C_MID + C_IN
#define C_DW   384        // C_CAT * DMUL
#define KK     256        // K*K
#define EPSV   1e-5f

// ---------------------------------------------------------------------------
// Scratch (static device memory -- allocation-free)
// ---------------------------------------------------------------------------
__device__ float g_ptsl[NPTS * 48];           // pts_local, layout [p][d*16+k]  (3 MB)
__device__ float g_lift[NPTS * KNB * C_MID];  // fts_lifted [p*16+k][64]        (64 MB)
__device__ float g_X[NPTS * KK];              // X0 / X2 buffer                 (16 MB)
__device__ float g_Xb[NPTS * KK];             // X1 buffer                      (16 MB)
__device__ float g_dw[NPTS * C_DW];           // depthwise output               (25 MB)
__device__ float g_psum [256 * C_OUT];        // BN partial sums
__device__ float g_psum2[256 * C_OUT];
__device__ float g_mean[C_OUT];
__device__ float g_istd[C_OUT];

// ---------------------------------------------------------------------------
// K1: pts_local + point-lifting MLP (d1 -> relu -> d2 -> relu)
// One thread per (point, neighbor) row. h recomputed on the fly (3 FMA/elem)
// to avoid a 64-reg h array; accumulators are 32 regs (half of 64 outputs).
// ---------------------------------------------------------------------------
__global__ __launch_bounds__(256) void k_lift(
    const float* __restrict__ rep, const float* __restrict__ pts,
    const float* __restrict__ d1w, const float* __restrict__ d1b,
    const float* __restrict__ d2w, const float* __restrict__ d2b)
{
    __shared__ float s_d1[3 * 64];
    __shared__ float s_d1b[64];
    __shared__ float s_d2[64 * 64];
    __shared__ float s_d2b[64];

    int t = threadIdx.x;
    for (int i = t; i < 64 * 64; i += 256) s_d2[i] = d2w[i];
    if (t < 192) s_d1[t] = d1w[t];
    if (t < 64) { s_d1b[t] = d1b[t]; s_d2b[t] = d2b[t]; }
    __syncthreads();

    int r = blockIdx.x * 256 + t;     // row in [0, NPTS*16)
    int p = r >> 4;
    int k = r & 15;

    float x = pts[r * 3 + 0] - rep[p * 3 + 0];
    float y = pts[r * 3 + 1] - rep[p * 3 + 1];
    float z = pts[r * 3 + 2] - rep[p * 3 + 2];

    // store pts_local in [d*16 + k] order so X0 becomes a GEMM
    g_ptsl[p * 48 +  0 + k] = x;
    g_ptsl[p * 48 + 16 + k] = y;
    g_ptsl[p * 48 + 32 + k] = z;

    #pragma unroll
    for (int half = 0; half < 2; half++) {
        float4 acc[8];
        #pragma unroll
        for (int q = 0; q < 8; q++) {
            acc[q].x = s_d2b[half * 32 + q * 4 + 0];
            acc[q].y = s_d2b[half * 32 + q * 4 + 1];
            acc[q].z = s_d2b[half * 32 + q * 4 + 2];
            acc[q].w = s_d2b[half * 32 + q * 4 + 3];
        }
        for (int i = 0; i < 64; i++) {
            float hv = fmaxf(s_d1b[i] + x * s_d1[i] + y * s_d1[64 + i] + z * s_d1[128 + i], 0.f);
            const float4* row = (const float4*)(s_d2 + i * 64 + half * 32);
            #pragma unroll
            for (int q = 0; q < 8; q++) {
                float4 w = row[q];
                acc[q].x += hv * w.x; acc[q].y += hv * w.y;
                acc[q].z += hv * w.z; acc[q].w += hv * w.w;
            }
        }
        float4* out = (float4*)(g_lift + (size_t)r * 64 + half * 32);
        #pragma unroll
        for (int q = 0; q < 8; q++) {
            float4 v = acc[q];
            v.x = fmaxf(v.x, 0.f); v.y = fmaxf(v.y, 0.f);
            v.z = fmaxf(v.z, 0.f); v.w = fmaxf(v.w, 0.f);
            out[q] = v;
        }
    }
}

// ---------------------------------------------------------------------------
// Tiled fp32 GEMM: C[M,N] = op(A[M,K] x B) (+bias) (relu)
//   BT = false: B is [K][N] row-major (i.e. A @ B)
//   BT = true : B is [N][K] row-major (i.e. A @ B^T)
// BM=BN=64, BK=16, 256 threads, 4x4 per thread.
// ---------------------------------------------------------------------------
template <bool BT, bool RELU, bool BIAS>
__global__ __launch_bounds__(256) void k_gemm(
    const float* __restrict__ A, const float* __restrict__ B,
    const float* __restrict__ bias, float* __restrict__ C,
    int M, int N, int K)
{
    __shared__ float As[16][68];
    __shared__ float Bs[16][68];

    int t = threadIdx.x;
    int row0 = blockIdx.x * 64;
    int col0 = blockIdx.y * 64;
    int ty = t >> 4, tx = t & 15;

    float acc[4][4] = {};

    int am = t >> 2;           // A loader: row within tile
    int ak = (t & 3) * 4;      // A loader: k within tile

    for (int k0 = 0; k0 < K; k0 += 16) {
        float4 av = *(const float4*)(A + (size_t)(row0 + am) * K + k0 + ak);
        As[ak + 0][am] = av.x; As[ak + 1][am] = av.y;
        As[ak + 2][am] = av.z; As[ak + 3][am] = av.w;

        if (BT) {
            int bn = t >> 2, bk = (t & 3) * 4;
            float4 bv = *(const float4*)(B + (size_t)(col0 + bn) * K + k0 + bk);
            Bs[bk + 0][bn] = bv.x; Bs[bk + 1][bn] = bv.y;
            Bs[bk + 2][bn] = bv.z; Bs[bk + 3][bn] = bv.w;
        } else {
            int bn = (t & 15) * 4, bk = t >> 4;
            float4 bv = *(const float4*)(B + (size_t)(k0 + bk) * N + col0 + bn);
            *(float4*)(&Bs[bk][bn]) = bv;
        }
        __syncthreads();

        #pragma unroll
        for (int k = 0; k < 16; k++) {
            float4 a = *(const float4*)(&As[k][ty * 4]);
            float4 b = *(const float4*)(&Bs[k][tx * 4]);
            float ar[4] = {a.x, a.y, a.z, a.w};
            float br[4] = {b.x, b.y, b.z, b.w};
            #pragma unroll
            for (int i = 0; i < 4; i++)
                #pragma unroll
                for (int j = 0; j < 4; j++)
                    acc[i][j] += ar[i] * br[j];
        }
        __syncthreads();
    }

    int cc = col0 + tx * 4;
    float4 bv = make_float4(0.f, 0.f, 0.f, 0.f);
    if (BIAS) {
        bv.x = __ldg(bias + cc + 0); bv.y = __ldg(bias + cc + 1);
        bv.z = __ldg(bias + cc + 2); bv.w = __ldg(bias + cc + 3);
    }
    #pragma unroll
    for (int i = 0; i < 4; i++) {
        int rr = row0 + ty * 4 + i;
        float4 v;
        v.x = acc[i][0] + bv.x; v.y = acc[i][1] + bv.y;
        v.z = acc[i][2] + bv.z; v.w = acc[i][3] + bv.w;
        if (RELU) {
            v.x = fmaxf(v.x, 0.f); v.y = fmaxf(v.y, 0.f);
            v.z = fmaxf(v.z, 0.f); v.w = fmaxf(v.w, 0.f);
        }
        *(float4*)(C + (size_t)rr * N + cc) = v;
    }
}

// ---------------------------------------------------------------------------
// K4: per-point X-transform apply + depthwise conv, fully fused.
//   fts_X[k,c] = sum_j X2[k,j] * cat[j,c]   (cat = [lifted(64) | fts(128)])
//   dw[c,m]    = sum_k fts_X[k,c] * dw_w[c,m,k] + dw_b[c*2+m]
// fts_X never hits memory: thread c keeps u[16] in registers.
// ---------------------------------------------------------------------------
__global__ __launch_bounds__(256) void k_trans(
    const float* __restrict__ fts, const float* __restrict__ dww,
    const float* __restrict__ dwb)
{
    __shared__ float sX[256];            // X2 for one point
    __shared__ float sc[16 * 192];       // fts_cat
    __shared__ float sw[32 * 192];       // dw_w transposed: [(m*16+k)*192 + c]

    int t = threadIdx.x;
    for (int s = t; s < C_CAT * DMUL * KNB; s += 256) {
        int c = s >> 5, m = (s >> 4) & 1, k = s & 15;
        sw[(m * 16 + k) * 192 + c] = dww[s];
    }

    int p0 = blockIdx.x * 8;
    for (int pi = 0; pi < 8; pi++) {
        int p = p0 + pi;
        __syncthreads();   // previous iteration's readers done before overwrite
        sX[t] = g_X[(size_t)p * 256 + t];
        for (int s = t; s < 16 * 64; s += 256) {
            int j = s >> 6, c = s & 63;
            sc[j * 192 + c] = g_lift[((size_t)p * 16 + j) * 64 + c];
        }
        for (int s = t; s < 16 * 128; s += 256) {
            int j = s >> 7, c = s & 127;
            sc[j * 192 + 64 + c] = fts[((size_t)p * 16 + j) * 128 + c];
        }
        __syncthreads();

        if (t < 192) {
            int c = t;
            float u[16];
            #pragma unroll
            for (int k = 0; k < 16; k++) u[k] = 0.f;
            for (int j = 0; j < 16; j++) {
                float cj = sc[j * 192 + c];
                #pragma unroll
                for (int k = 0; k < 16; k++) u[k] += sX[k * 16 + j] * cj;
            }
            #pragma unroll
            for (int m = 0; m < 2; m++) {
                float acc = __ldg(dwb + c * 2 + m);
                #pragma unroll
                for (int k = 0; k < 16; k++) acc += u[k] * sw[(m * 16 + k) * 192 + c];
                g_dw[(size_t)p * 384 + c * 2 + m] = acc;
            }
        }
    }
}

// ---------------------------------------------------------------------------
// BN: deterministic two-level reduction, then normalize in place.
// ---------------------------------------------------------------------------
__global__ __launch_bounds__(256) void k_red1(const float* __restrict__ out)
{
    int b = blockIdx.x, t = threadIdx.x;
    float s = 0.f, s2 = 0.f;
    const float* base = out + (size_t)b * 64 * 256 + t;
    #pragma unroll 4
    for (int r = 0; r < 64; r++) {
        float v = base[(size_t)r * 256];
        s += v; s2 += v * v;
    }
    g_psum [b * 256 + t] = s;
    g_psum2[b * 256 + t] = s2;
}

__global__ __launch_bounds__(256) void k_red2()
{
    int t = threadIdx.x;
    float s = 0.f, s2 = 0.f;
    for (int b = 0; b < 256; b++) {
        s  += g_psum [b * 256 + t];
        s2 += g_psum2[b * 256 + t];
    }
    const float inv = 1.f / (float)NPTS;
    float mean = s * inv;
    float var  = s2 * inv - mean * mean;
    g_mean[t] = mean;
    g_istd[t] = rsqrtf(var + EPSV);
}

__global__ __launch_bounds__(256) void k_bn(
    float* __restrict__ out,
    const float* __restrict__ bng, const float* __restrict__ bnb)
{
    int idx = blockIdx.x * 256 + threadIdx.x;
    int ch = idx & 255;
    float v = out[idx];
    out[idx] = (v - g_mean[ch]) * g_istd[ch] * __ldg(bng + ch) + __ldg(bnb + ch);
}

// ---------------------------------------------------------------------------
// Launch
// ---------------------------------------------------------------------------
static float* sym_addr(const void* sym)
{
    void* p = nullptr;
    cudaGetSymbolAddress(&p, sym);
    return (float*)p;
}

extern "C" void kernel_launch(void* const* d_in, const int* in_sizes, int n_in,
                              void* d_out, int out_size)
{
    const float* rep = (const float*)d_in[0];
    const float* pts = (const float*)d_in[1];
    const float* fts = (const float*)d_in[2];
    const float* d1w = (const float*)d_in[3];
    const float* d1b = (const float*)d_in[4];
    const float* d2w = (const float*)d_in[5];
    const float* d2b = (const float*)d_in[6];
    const float* cvw = (const float*)d_in[7];
    const float* cvb = (const float*)d_in[8];
    const float* x1w = (const float*)d_in[9];
    const float* x1b = (const float*)d_in[10];
    const float* x2w = (const float*)d_in[11];
    const float* x2b = (const float*)d_in[12];
    const float* dww = (const float*)d_in[13];
    const float* dwb = (const float*)d_in[14];
    const float* pww = (const float*)d_in[15];
    const float* bng = (const float*)d_in[16];
    const float* bnb = (const float*)d_in[17];
    float* out = (float*)d_out;

    float* p_ptsl = sym_addr(g_ptsl);
    float* p_X    = sym_addr(g_X);
    float* p_Xb   = sym_addr(g_Xb);
    float* p_dw   = sym_addr(g_dw);

    // 1. pts_local + lifting MLP
    k_lift<<<NPTS * KNB / 256, 256>>>(rep, pts, d1w, d1b, d2w, d2b);

    // 2. X0 = relu(pts_local48 @ cv_w^T + cv_b)    [16384,48]x[48,256]
    k_gemm<true, true, true><<<dim3(NPTS / 64, KK / 64), 256>>>(
        p_ptsl, cvw, cvb, p_X, NPTS, KK, 48);

    // 3. X1 = relu(X0 @ x1_w + x1_b)               [16384,256]x[256,256]
    k_gemm<false, true, true><<<dim3(NPTS / 64, KK / 64), 256>>>(
        p_X, x1w, x1b, p_Xb, NPTS, KK, KK);

    // 4. X2 = X1 @ x2_w + x2_b
    k_gemm<false, false, true><<<dim3(NPTS / 64, KK / 64), 256>>>(
        p_Xb, x2w, x2b, p_X, NPTS, KK, KK);

    // 5. fts_X + depthwise (fused)
    k_trans<<<NPTS / 8, 256>>>(fts, dww, dwb);

    // 6. out = relu(dw @ pw_w^T)                   [16384,384]x[384,256]
    k_gemm<true, true, false><<<dim3(NPTS / 64, C_OUT / 64), 256>>>(
        p_dw, pww, nullptr, out, NPTS, C_OUT, C_DW);

    // 7-9. BatchNorm (deterministic)
    k_red1<<<256, 256>>>(out);
    k_red2<<<1, 256>>>();
    k_bn<<<NPTS * C_OUT / 256, 256>>>(out, bng, bnb);
}

// round 3
// speedup vs baseline: 1.1327x; 1.1327x over previous
#include <cuda_runtime.h>
#include <cstdio>

// ---------------------------------------------------------------------------
// Problem constants
// ---------------------------------------------------------------------------
#define NPTS   16384      // N*P
#define KNB    16         // K neighbors
#define C_IN   128
#define C_MID  64
#define C_OUT  256
#define DMUL   2
#define C_CAT  192        // C_MID + C_IN
#define C_DW   384        // C_CAT * DMUL
#define KK     256        // K*K
#define EPSV   1e-5f

typedef unsigned long long ull;

// ---------------------------------------------------------------------------
// Packed f32x2 helpers (Blackwell 2x FP32 path; ptxas never emits these)
// ---------------------------------------------------------------------------
__device__ __forceinline__ ull fma2(ull a, ull b, ull c) {
    ull d;
    asm("fma.rn.f32x2 %0, %1, %2, %3;" : "=l"(d) : "l"(a), "l"(b), "l"(c));
    return d;
}
__device__ __forceinline__ ull dup2(float x) {
    ull d;
    asm("mov.b64 %0, {%1, %1};" : "=l"(d) : "f"(x));
    return d;
}
__device__ __forceinline__ void unpack2(ull v, float& lo, float& hi) {
    asm("mov.b64 {%0, %1}, %2;" : "=f"(lo), "=f"(hi) : "l"(v));
}

// ---------------------------------------------------------------------------
// Scratch (static device memory -- allocation-free)
// ---------------------------------------------------------------------------
__device__ __align__(16) float g_ptsl[NPTS * 48];           // pts_local, [p][d*16+k]
__device__ __align__(16) float g_lift[NPTS * KNB * C_MID];  // fts_lifted [p*16+k][64]
__device__ __align__(16) float g_X[NPTS * KK];              // X0 / X2 buffer
__device__ __align__(16) float g_Xb[NPTS * KK];             // X1 buffer
__device__ __align__(16) float g_dw[NPTS * C_DW];           // depthwise output
__device__ float g_psum [256 * C_OUT];
__device__ float g_psum2[256 * C_OUT];
__device__ float g_mean[C_OUT];
__device__ float g_istd[C_OUT];

// ---------------------------------------------------------------------------
// K1: pts_local + point-lifting MLP (d1 -> relu -> d2 -> relu), f32x2 accs.
// One thread per (point, neighbor). 32 packed accumulators = 64 channels.
// ---------------------------------------------------------------------------
__global__ __launch_bounds__(256) void k_lift(
    const float* __restrict__ rep, const float* __restrict__ pts,
    const float* __restrict__ d1w, const float* __restrict__ d1b,
    const float* __restrict__ d2w, const float* __restrict__ d2b)
{
    __shared__ __align__(16) float s_d1[3 * 64];
    __shared__ __align__(16) float s_d1b[64];
    __shared__ __align__(16) float s_d2[64 * 64];
    __shared__ __align__(16) float s_d2b[64];

    int t = threadIdx.x;
    for (int i = t; i < 64 * 64; i += 256) s_d2[i] = d2w[i];
    if (t < 192) s_d1[t] = d1w[t];
    if (t < 64) { s_d1b[t] = d1b[t]; s_d2b[t] = d2b[t]; }
    __syncthreads();

    int r = blockIdx.x * 256 + t;     // row in [0, NPTS*16)
    int p = r >> 4;
    int k = r & 15;

    float x = pts[r * 3 + 0] - rep[p * 3 + 0];
    float y = pts[r * 3 + 1] - rep[p * 3 + 1];
    float z = pts[r * 3 + 2] - rep[p * 3 + 2];

    g_ptsl[p * 48 +  0 + k] = x;
    g_ptsl[p * 48 + 16 + k] = y;
    g_ptsl[p * 48 + 32 + k] = z;

    ull acc[32];
    const ull* biasp = (const ull*)s_d2b;
    #pragma unroll
    for (int q = 0; q < 32; q++) acc[q] = biasp[q];

    for (int i = 0; i < 64; i++) {
        float hv = fmaxf(s_d1b[i] + x * s_d1[i] + y * s_d1[64 + i] + z * s_d1[128 + i], 0.f);
        ull hd = dup2(hv);
        const ulonglong2* row = (const ulonglong2*)(s_d2 + i * 64);
        #pragma unroll
        for (int q2 = 0; q2 < 16; q2++) {
            ulonglong2 w2 = row[q2];
            acc[2 * q2 + 0] = fma2(hd, w2.x, acc[2 * q2 + 0]);
            acc[2 * q2 + 1] = fma2(hd, w2.y, acc[2 * q2 + 1]);
        }
    }

    float* out = g_lift + (size_t)r * 64;
    #pragma unroll
    for (int b = 0; b < 16; b++) {
        float f0, f1, f2, f3;
        unpack2(acc[2 * b + 0], f0, f1);
        unpack2(acc[2 * b + 1], f2, f3);
        float4 v;
        v.x = fmaxf(f0, 0.f); v.y = fmaxf(f1, 0.f);
        v.z = fmaxf(f2, 0.f); v.w = fmaxf(f3, 0.f);
        *(float4*)(out + b * 4) = v;
    }
}

// ---------------------------------------------------------------------------
// Tiled fp32 GEMM with packed f32x2 FMA.
// C[M,N] = op(A[M,K] x B) (+bias) (relu)
//   BT=false: B is [K][N].  BT=true: B is [N][K].
// BM=BN=128, BK=16, 256 threads, 8x8 per thread (split 4+4 quads),
// double-buffered smem.
// ---------------------------------------------------------------------------
template <bool BT, bool RELU, bool BIAS>
__global__ __launch_bounds__(256) void k_gemm(
    const float* __restrict__ A, const float* __restrict__ B,
    const float* __restrict__ bias, float* __restrict__ C,
    int M, int N, int K)
{
    __shared__ __align__(16) float As[2][16][132];
    __shared__ __align__(16) float Bs[2][16][132];

    int t = threadIdx.x;
    int row0 = blockIdx.x * 128;
    int col0 = blockIdx.y * 128;
    int ty = t >> 4, tx = t & 15;

    ull acc[2][4][4];
    #pragma unroll
    for (int a = 0; a < 2; a++)
        #pragma unroll
        for (int i = 0; i < 4; i++)
            #pragma unroll
            for (int j = 0; j < 4; j++)
                acc[a][i][j] = 0ull;

    // A loader: 2 contiguous float4 per thread
    int am = t >> 1;
    int ak = (t & 1) * 8;
    const float* Aptr = A + (size_t)(row0 + am) * K + ak;

    // B loader
    int bn, bk;
    const float* Bptr;
    if (BT) { bn = t >> 1;  bk = (t & 1) * 8;  Bptr = B + (size_t)(col0 + bn) * K + bk; }
    else    { bk = t >> 4;  bn = (t & 15) * 8; Bptr = B + (size_t)bk * N + col0 + bn; }

    int KT = K >> 4;

    float4 a0 = *(const float4*)(Aptr);
    float4 a1 = *(const float4*)(Aptr + 4);
    float4 b0 = *(const float4*)(Bptr);
    float4 b1 = *(const float4*)(Bptr + 4);

    // store tile 0
    {
        As[0][ak + 0][am] = a0.x; As[0][ak + 1][am] = a0.y;
        As[0][ak + 2][am] = a0.z; As[0][ak + 3][am] = a0.w;
        As[0][ak + 4][am] = a1.x; As[0][ak + 5][am] = a1.y;
        As[0][ak + 6][am] = a1.z; As[0][ak + 7][am] = a1.w;
        if (BT) {
            Bs[0][bk + 0][bn] = b0.x; Bs[0][bk + 1][bn] = b0.y;
            Bs[0][bk + 2][bn] = b0.z; Bs[0][bk + 3][bn] = b0.w;
            Bs[0][bk + 4][bn] = b1.x; Bs[0][bk + 5][bn] = b1.y;
            Bs[0][bk + 6][bn] = b1.z; Bs[0][bk + 7][bn] = b1.w;
        } else {
            *(float4*)&Bs[0][bk][bn] = b0;
            *(float4*)&Bs[0][bk][bn + 4] = b1;
        }
    }
    __syncthreads();

    for (int kt = 0; kt < KT; kt++) {
        int cur = kt & 1;
        bool more = (kt + 1 < KT);
        if (more) {
            Aptr += 16;
            a0 = *(const float4*)(Aptr);
            a1 = *(const float4*)(Aptr + 4);
            Bptr += BT ? 16 : (size_t)16 * N;
            b0 = *(const float4*)(Bptr);
            b1 = *(const float4*)(Bptr + 4);
        }

        #pragma unroll
        for (int k = 0; k < 16; k++) {
            float4 av0 = *(const float4*)&As[cur][k][ty * 4];
            float4 av1 = *(const float4*)&As[cur][k][64 + ty * 4];
            ulonglong2 bv0 = *(const ulonglong2*)&Bs[cur][k][tx * 4];
            ulonglong2 bv1 = *(const ulonglong2*)&Bs[cur][k][64 + tx * 4];
            ull bp0 = bv0.x, bp1 = bv0.y, bp2 = bv1.x, bp3 = bv1.y;

            float ar0[4] = {av0.x, av0.y, av0.z, av0.w};
            float ar1[4] = {av1.x, av1.y, av1.z, av1.w};
            #pragma unroll
            for (int i = 0; i < 4; i++) {
                ull ad = dup2(ar0[i]);
                acc[0][i][0] = fma2(ad, bp0, acc[0][i][0]);
                acc[0][i][1] = fma2(ad, bp1, acc[0][i][1]);
                acc[0][i][2] = fma2(ad, bp2, acc[0][i][2]);
                acc[0][i][3] = fma2(ad, bp3, acc[0][i][3]);
            }
            #pragma unroll
            for (int i = 0; i < 4; i++) {
                ull ad = dup2(ar1[i]);
                acc[1][i][0] = fma2(ad, bp0, acc[1][i][0]);
                acc[1][i][1] = fma2(ad, bp1, acc[1][i][1]);
                acc[1][i][2] = fma2(ad, bp2, acc[1][i][2]);
                acc[1][i][3] = fma2(ad, bp3, acc[1][i][3]);
            }
        }

        if (more) {
            int nxt = cur ^ 1;
            As[nxt][ak + 0][am] = a0.x; As[nxt][ak + 1][am] = a0.y;
            As[nxt][ak + 2][am] = a0.z; As[nxt][ak + 3][am] = a0.w;
            As[nxt][ak + 4][am] = a1.x; As[nxt][ak + 5][am] = a1.y;
            As[nxt][ak + 6][am] = a1.z; As[nxt][ak + 7][am] = a1.w;
            if (BT) {
                Bs[nxt][bk + 0][bn] = b0.x; Bs[nxt][bk + 1][bn] = b0.y;
                Bs[nxt][bk + 2][bn] = b0.z; Bs[nxt][bk + 3][bn] = b0.w;
                Bs[nxt][bk + 4][bn] = b1.x; Bs[nxt][bk + 5][bn] = b1.y;
                Bs[nxt][bk + 6][bn] = b1.z; Bs[nxt][bk + 7][bn] = b1.w;
            } else {
                *(float4*)&Bs[nxt][bk][bn] = b0;
                *(float4*)&Bs[nxt][bk][bn + 4] = b1;
            }
        }
        __syncthreads();
    }

    // epilogue
    float4 bvec[2] = {make_float4(0.f,0.f,0.f,0.f), make_float4(0.f,0.f,0.f,0.f)};
    if (BIAS) {
        bvec[0] = *(const float4*)(bias + col0 + tx * 4);
        bvec[1] = *(const float4*)(bias + col0 + 64 + tx * 4);
    }
    #pragma unroll
    for (int rh = 0; rh < 2; rh++) {
        #pragma unroll
        for (int i = 0; i < 4; i++) {
            int rr = row0 + rh * 64 + ty * 4 + i;
            #pragma unroll
            for (int ch = 0; ch < 2; ch++) {
                int cc = col0 + ch * 64 + tx * 4;
                float f0, f1, f2, f3;
                unpack2(acc[rh][i][ch * 2 + 0], f0, f1);
                unpack2(acc[rh][i][ch * 2 + 1], f2, f3);
                float4 v;
                v.x = f0 + bvec[ch].x; v.y = f1 + bvec[ch].y;
                v.z = f2 + bvec[ch].z; v.w = f3 + bvec[ch].w;
                if (RELU) {
                    v.x = fmaxf(v.x, 0.f); v.y = fmaxf(v.y, 0.f);
                    v.z = fmaxf(v.z, 0.f); v.w = fmaxf(v.w, 0.f);
                }
                *(float4*)(C + (size_t)rr * N + cc) = v;
            }
        }
    }
}

// ---------------------------------------------------------------------------
// K4: per-point X-transform apply + depthwise conv, f32x2.
//   fts_X[k,c] = sum_j X[k,j] * cat[j,c]   (cat = [lifted(64) | fts(128)])
//   dw[c,m]    = sum_k fts_X[k,c] * dw_w[c,m,k] + dw_b[c*2+m]
// 192 threads (one per channel), u[] kept as 8 packed pairs over k.
// ---------------------------------------------------------------------------
#define TR_PTS 8
__global__ __launch_bounds__(192) void k_trans(
    const float* __restrict__ fts, const float* __restrict__ dww,
    const float* __restrict__ dwb)
{
    __shared__ __align__(16) float  sXT[16][20];      // X transposed: [j][k], padded
    __shared__ __align__(16) float  sc[16][192];      // cat [j][c]
    __shared__ __align__(16) float2 swq[2][8][192];   // dw_w k-pairs: [m][kp][c]

    int t = threadIdx.x;
    for (int s = t; s < 2 * 8 * 192; s += 192) {
        int c  = s % 192;
        int kp = (s / 192) & 7;
        int m  = s / (192 * 8);
        swq[m][kp][c] = make_float2(dww[c * 32 + m * 16 + 2 * kp],
                                    dww[c * 32 + m * 16 + 2 * kp + 1]);
    }

    int p0 = blockIdx.x * TR_PTS;
    for (int pi = 0; pi < TR_PTS; pi++) {
        int p = p0 + pi;
        __syncthreads();  // previous iteration's readers done

        // X: g_X row o = kout*16 + j  ->  sXT[j][kout]
        for (int s = t; s < 256; s += 192)
            sXT[s & 15][s >> 4] = g_X[(size_t)p * 256 + s];
        // cat: lifted part (64 ch) as float4
        for (int s = t; s < 256; s += 192) {
            int j = s >> 4, c4 = (s & 15) * 4;
            *(float4*)&sc[j][c4] = *(const float4*)&g_lift[((size_t)p * 16 + j) * 64 + c4];
        }
        // cat: fts part (128 ch) as float4
        for (int s = t; s < 512; s += 192) {
            int j = s >> 5, c4 = (s & 31) * 4;
            *(float4*)&sc[j][64 + c4] = *(const float4*)&fts[((size_t)p * 16 + j) * 128 + c4];
        }
        __syncthreads();

        int c = t;
        ull u[8];
        #pragma unroll
        for (int q = 0; q < 8; q++) u[q] = 0ull;

        #pragma unroll
        for (int j = 0; j < 16; j++) {
            ull cj = dup2(sc[j][c]);
            ulonglong2 x0 = *(const ulonglong2*)&sXT[j][0];
            ulonglong2 x1 = *(const ulonglong2*)&sXT[j][4];
            ulonglong2 x2 = *(const ulonglong2*)&sXT[j][8];
            ulonglong2 x3 = *(const ulonglong2*)&sXT[j][12];
            u[0] = fma2(cj, x0.x, u[0]); u[1] = fma2(cj, x0.y, u[1]);
            u[2] = fma2(cj, x1.x, u[2]); u[3] = fma2(cj, x1.y, u[3]);
            u[4] = fma2(cj, x2.x, u[4]); u[5] = fma2(cj, x2.y, u[5]);
            u[6] = fma2(cj, x3.x, u[6]); u[7] = fma2(cj, x3.y, u[7]);
        }

        #pragma unroll
        for (int m = 0; m < 2; m++) {
            ull s2 = 0ull;
            #pragma unroll
            for (int kp = 0; kp < 8; kp++) {
                ull w2 = *(const ull*)&swq[m][kp][c];
                s2 = fma2(u[kp], w2, s2);
            }
            float lo, hi;
            unpack2(s2, lo, hi);
            g_dw[(size_t)p * 384 + c * 2 + m] = lo + hi + __ldg(dwb + c * 2 + m);
        }
    }
}

// ---------------------------------------------------------------------------
// BN: deterministic two-level reduction, then normalize in place.
// ---------------------------------------------------------------------------
__global__ __launch_bounds__(256) void k_red1(const float* __restrict__ out)
{
    int b = blockIdx.x, t = threadIdx.x;
    float s = 0.f, s2 = 0.f;
    const float* base = out + (size_t)b * 64 * 256 + t;
    #pragma unroll 4
    for (int r = 0; r < 64; r++) {
        float v = base[(size_t)r * 256];
        s += v; s2 += v * v;
    }
    g_psum [b * 256 + t] = s;
    g_psum2[b * 256 + t] = s2;
}

__global__ __launch_bounds__(256) void k_red2()
{
    int t = threadIdx.x;
    float s = 0.f, s2 = 0.f;
    for (int b = 0; b < 256; b++) {
        s  += g_psum [b * 256 + t];
        s2 += g_psum2[b * 256 + t];
    }
    const float inv = 1.f / (float)NPTS;
    float mean = s * inv;
    float var  = s2 * inv - mean * mean;
    g_mean[t] = mean;
    g_istd[t] = rsqrtf(var + EPSV);
}

__global__ __launch_bounds__(256) void k_bn(
    float* __restrict__ out,
    const float* __restrict__ bng, const float* __restrict__ bnb)
{
    int idx = blockIdx.x * 256 + threadIdx.x;
    int ch = idx & 255;
    float v = out[idx];
    out[idx] = (v - g_mean[ch]) * g_istd[ch] * __ldg(bng + ch) + __ldg(bnb + ch);
}

// ---------------------------------------------------------------------------
// Launch
// ---------------------------------------------------------------------------
static float* sym_addr(const void* sym)
{
    void* p = nullptr;
    cudaGetSymbolAddress(&p, sym);
    return (float*)p;
}

extern "C" void kernel_launch(void* const* d_in, const int* in_sizes, int n_in,
                              void* d_out, int out_size)
{
    const float* rep = (const float*)d_in[0];
    const float* pts = (const float*)d_in[1];
    const float* fts = (const float*)d_in[2];
    const float* d1w = (const float*)d_in[3];
    const float* d1b = (const float*)d_in[4];
    const float* d2w = (const float*)d_in[5];
    const float* d2b = (const float*)d_in[6];
    const float* cvw = (const float*)d_in[7];
    const float* cvb = (const float*)d_in[8];
    const float* x1w = (const float*)d_in[9];
    const float* x1b = (const float*)d_in[10];
    const float* x2w = (const float*)d_in[11];
    const float* x2b = (const float*)d_in[12];
    const float* dww = (const float*)d_in[13];
    const float* dwb = (const float*)d_in[14];
    const float* pww = (const float*)d_in[15];
    const float* bng = (const float*)d_in[16];
    const float* bnb = (const float*)d_in[17];
    float* out = (float*)d_out;

    float* p_ptsl = sym_addr(g_ptsl);
    float* p_X    = sym_addr(g_X);
    float* p_Xb   = sym_addr(g_Xb);
    float* p_dw   = sym_addr(g_dw);

    // 1. pts_local + lifting MLP
    k_lift<<<NPTS * KNB / 256, 256>>>(rep, pts, d1w, d1b, d2w, d2b);

    // 2. X0 = relu(pts_local48 @ cv_w^T + cv_b)    [16384,48]x[48,256]
    k_gemm<true, true, true><<<dim3(NPTS / 128, KK / 128), 256>>>(
        p_ptsl, cvw, cvb, p_X, NPTS, KK, 48);

    // 3. X1 = relu(X0 @ x1_w + x1_b)               [16384,256]x[256,256]
    k_gemm<false, true, true><<<dim3(NPTS / 128, KK / 128), 256>>>(
        p_X, x1w, x1b, p_Xb, NPTS, KK, KK);

    // 4. X2 = X1 @ x2_w + x2_b
    k_gemm<false, false, true><<<dim3(NPTS / 128, KK / 128), 256>>>(
        p_Xb, x2w, x2b, p_X, NPTS, KK, KK);

    // 5. fts_X + depthwise (fused)
    k_trans<<<NPTS / TR_PTS, 192>>>(fts, dww, dwb);

    // 6. out = relu(dw @ pw_w^T)                   [16384,384]x[384,256]
    k_gemm<true, true, false><<<dim3(NPTS / 128, C_OUT / 128), 256>>>(
        p_dw, pww, nullptr, out, NPTS, C_OUT, C_DW);

    // 7-9. BatchNorm (deterministic)
    k_red1<<<256, 256>>>(out);
    k_red2<<<1, 256>>>();
    k_bn<<<NPTS * C_OUT / 256, 256>>>(out, bng, bnb);
}